// round 1
// baseline (speedup 1.0000x reference)
#include <cuda_runtime.h>
#include <cuda_bf16.h>

// Problem constants
#define BATCH 4
#define HW    65536          // 256*256
#define KBINS 512            // 8^3
// -1 / (49 * 2*sigma^2)  with sigma = 0.02  ->  -1/(49*0.0008)
#define NEG_COEF (-25.510204081632653f)

// Scratch accumulator (no cudaMalloc allowed)
__device__ float g_hist[BATCH * KBINS];

__global__ void dh_zero_kernel() {
    int i = blockIdx.x * blockDim.x + threadIdx.x;
    if (i < BATCH * KBINS) g_hist[i] = 0.0f;
}

__global__ void dh_accum_kernel(const float* __restrict__ x) {
    __shared__ float sh[KBINS];
    const int b = blockIdx.y;

    for (int i = threadIdx.x; i < KBINS; i += blockDim.x) sh[i] = 0.0f;
    __syncthreads();

    const float* __restrict__ xb = x + (size_t)b * 3 * HW;
    const int stride = gridDim.x * blockDim.x;

    for (int p = blockIdx.x * blockDim.x + threadIdx.x; p < HW; p += stride) {
        const float vx = xb[p];
        const float vy = xb[HW + p];
        const float vz = xb[2 * HW + p];

        // per-channel nearest-two-bins decomposition (bin spacing = 1/7)
        float tx = vx * 7.0f;
        float ty = vy * 7.0f;
        float tz = vz * 7.0f;
        int ix = min((int)tx, 6);
        int iy = min((int)ty, 6);
        int iz = min((int)tz, 6);
        float fx = tx - (float)ix;
        float fy = ty - (float)iy;
        float fz = tz - (float)iz;

        float gx = 1.0f - fx, gy = 1.0f - fy, gz = 1.0f - fz;

        float wx0 = __expf(NEG_COEF * fx * fx);
        float wx1 = __expf(NEG_COEF * gx * gx);
        float wy0 = __expf(NEG_COEF * fy * fy);
        float wy1 = __expf(NEG_COEF * gy * gy);
        float wz0 = __expf(NEG_COEF * fz * fz);
        float wz1 = __expf(NEG_COEF * gz * gz);

        // per-pixel normalizer (factorized), keep the +1e-8 (it matters: S >= ~4e-8)
        float S = (wx0 + wx1) * (wy0 + wy1) * (wz0 + wz1);
        float inv = __fdividef(1.0f, S + 1e-8f);

        // scale z-pair by inv once (saves 4 mults)
        wz0 *= inv;
        wz1 *= inv;

        float wyz00 = wy0 * wz0, wyz01 = wy0 * wz1;
        float wyz10 = wy1 * wz0, wyz11 = wy1 * wz1;

        const int base = ix * 64 + iy * 8 + iz;
        atomicAdd(&sh[base +  0], wx0 * wyz00);
        atomicAdd(&sh[base +  1], wx0 * wyz01);
        atomicAdd(&sh[base +  8], wx0 * wyz10);
        atomicAdd(&sh[base +  9], wx0 * wyz11);
        atomicAdd(&sh[base + 64], wx1 * wyz00);
        atomicAdd(&sh[base + 65], wx1 * wyz01);
        atomicAdd(&sh[base + 72], wx1 * wyz10);
        atomicAdd(&sh[base + 73], wx1 * wyz11);
    }

    __syncthreads();
    for (int i = threadIdx.x; i < KBINS; i += blockDim.x) {
        float v = sh[i];
        if (v != 0.0f) atomicAdd(&g_hist[b * KBINS + i], v);
    }
}

__global__ void dh_norm_kernel(float* __restrict__ out) {
    const int b = blockIdx.x;
    const int t = threadIdx.x;     // 512 threads
    float v = g_hist[b * KBINS + t];

    // block reduction of 512 values
    __shared__ float red[16];
    float s = v;
    #pragma unroll
    for (int o = 16; o > 0; o >>= 1) s += __shfl_xor_sync(0xffffffffu, s, o);
    if ((t & 31) == 0) red[t >> 5] = s;
    __syncthreads();
    if (t < 16) {
        s = red[t];
        #pragma unroll
        for (int o = 8; o > 0; o >>= 1) s += __shfl_xor_sync(0x0000ffffu, s, o);
        if (t == 0) red[0] = s;
    }
    __syncthreads();

    out[b * KBINS + t] = __fdividef(v, red[0] + 1e-8f);
}

extern "C" void kernel_launch(void* const* d_in, const int* in_sizes, int n_in,
                              void* d_out, int out_size) {
    const float* x = (const float*)d_in[0];
    float* out = (float*)d_out;

    dh_zero_kernel<<<(BATCH * KBINS + 255) / 256, 256>>>();

    dim3 grid(74, BATCH);   // 296 CTAs = 2 per SM, one wave
    dh_accum_kernel<<<grid, 256>>>(x);

    dh_norm_kernel<<<BATCH, KBINS>>>(out);
}

// round 2
// speedup vs baseline: 1.1597x; 1.1597x over previous
#include <cuda_runtime.h>
#include <cuda_bf16.h>

#define BATCH 4
#define HW    65536           // 256*256 pixels per (batch,channel)
#define NF4   (HW / 4)        // 16384 float4s per channel
#define KBINS 512             // 8^3 bins
#define GX    74              // blocks per batch -> 296 CTAs = 2/SM, even work
// -1 / (49 * 2*sigma^2), sigma = 0.02
#define NEG_COEF (-25.510204081632653f)
// tail-truncation thresholds: far-bin relative weight at f=0.28 is
// exp(-25.5*(1-0.56)) = 1.34e-5 -> per-bin error ~1e-4 rel, tol is 1e-3
#define TLO 0.28f
#define THI 0.72f

// Scratch (no cudaMalloc allowed). Zero at module load; the last block per
// batch resets it to zero each run, preserving the invariant across graph
// replays. Deterministic: identical work every call.
__device__ float        g_hist[BATCH * KBINS];
__device__ unsigned int g_count[BATCH];

__global__ __launch_bounds__(256, 2)
void dh_fused_kernel(const float* __restrict__ x, float* __restrict__ out) {
    __shared__ float sh[KBINS];
    __shared__ int   s_last;
    __shared__ float red[8];

    const int b   = blockIdx.y;
    const int tid = threadIdx.x;

    for (int i = tid; i < KBINS; i += 256) sh[i] = 0.0f;
    __syncthreads();

    // ---- per-block contiguous float4 range: 221 or 222 per block ----
    const float* __restrict__ xb = x + (size_t)b * 3 * HW;
    const int start = (int)(((long long)blockIdx.x       * NF4) / GX);
    const int end   = (int)(((long long)(blockIdx.x + 1) * NF4) / GX);
    const int i4    = start + tid;

    if (i4 < end) {
        const float4 vx4 = __ldg((const float4*)(xb)          + i4);
        const float4 vy4 = __ldg((const float4*)(xb +     HW) + i4);
        const float4 vz4 = __ldg((const float4*)(xb + 2 * HW) + i4);
        const float* vxp = (const float*)&vx4;
        const float* vyp = (const float*)&vy4;
        const float* vzp = (const float*)&vz4;

        #pragma unroll
        for (int j = 0; j < 4; ++j) {
            const float tx = vxp[j] * 7.0f;
            const float ty = vyp[j] * 7.0f;
            const float tz = vzp[j] * 7.0f;
            const int ix = min((int)tx, 6);
            const int iy = min((int)ty, 6);
            const int iz = min((int)tz, 6);
            const float fx = tx - (float)ix;
            const float fy = ty - (float)iy;
            const float fz = tz - (float)iz;
            const float gx = 1.0f - fx, gy = 1.0f - fy, gz = 1.0f - fz;

            const float wx0 = __expf(NEG_COEF * fx * fx);
            const float wx1 = __expf(NEG_COEF * gx * gx);
            const float wy0 = __expf(NEG_COEF * fy * fy);
            const float wy1 = __expf(NEG_COEF * gy * gy);
            float       wz0 = __expf(NEG_COEF * fz * fz);
            float       wz1 = __expf(NEG_COEF * gz * gz);

            // exact per-pixel normalizer (all 6 weights; +1e-8 matters)
            const float S   = (wx0 + wx1) * (wy0 + wy1) * (wz0 + wz1);
            const float inv = __fdividef(1.0f, S + 1e-8f);
            wz0 *= inv;
            wz1 *= inv;

            // tail truncation: include a bin only if its per-axis relative
            // weight exceeds ~1.3e-5 (E[bins/axis]=1.44 -> ~3 atomics/pixel)
            const bool px0 = fx < THI, px1 = fx > TLO;
            const bool py0 = fy < THI, py1 = fy > TLO;
            const bool pz0 = fz < THI, pz1 = fz > TLO;

            const float wyz00 = wy0 * wz0, wyz01 = wy0 * wz1;
            const float wyz10 = wy1 * wz0, wyz11 = wy1 * wz1;
            const int base = ix * 64 + iy * 8 + iz;

            if (px0 && py0 && pz0) atomicAdd(&sh[base +  0], wx0 * wyz00);
            if (px0 && py0 && pz1) atomicAdd(&sh[base +  1], wx0 * wyz01);
            if (px0 && py1 && pz0) atomicAdd(&sh[base +  8], wx0 * wyz10);
            if (px0 && py1 && pz1) atomicAdd(&sh[base +  9], wx0 * wyz11);
            if (px1 && py0 && pz0) atomicAdd(&sh[base + 64], wx1 * wyz00);
            if (px1 && py0 && pz1) atomicAdd(&sh[base + 65], wx1 * wyz01);
            if (px1 && py1 && pz0) atomicAdd(&sh[base + 72], wx1 * wyz10);
            if (px1 && py1 && pz1) atomicAdd(&sh[base + 73], wx1 * wyz11);
        }
    }

    __syncthreads();

    // ---- flush block-private histogram to global ----
    for (int i = tid; i < KBINS; i += 256) {
        const float v = sh[i];
        if (v != 0.0f) atomicAdd(&g_hist[b * KBINS + i], v);
    }

    // ---- last block per batch normalizes, writes out, resets scratch ----
    __threadfence();
    if (tid == 0) {
        const unsigned t = atomicAdd(&g_count[b], 1u);
        s_last = (t == gridDim.x - 1) ? 1 : 0;
    }
    __syncthreads();

    if (s_last) {
        __threadfence();
        const float v0 = __ldcg(&g_hist[b * KBINS + tid]);
        const float v1 = __ldcg(&g_hist[b * KBINS + 256 + tid]);

        float s = v0 + v1;
        #pragma unroll
        for (int o = 16; o > 0; o >>= 1) s += __shfl_xor_sync(0xffffffffu, s, o);
        if ((tid & 31) == 0) red[tid >> 5] = s;
        __syncthreads();

        float total = 0.0f;
        #pragma unroll
        for (int k = 0; k < 8; ++k) total += red[k];

        const float inv = __fdividef(1.0f, total + 1e-8f);
        out[b * KBINS + tid]       = v0 * inv;
        out[b * KBINS + 256 + tid] = v1 * inv;

        // restore zero-invariant for the next graph replay
        g_hist[b * KBINS + tid]       = 0.0f;
        g_hist[b * KBINS + 256 + tid] = 0.0f;
        if (tid == 0) g_count[b] = 0u;
    }
}

extern "C" void kernel_launch(void* const* d_in, const int* in_sizes, int n_in,
                              void* d_out, int out_size) {
    const float* x = (const float*)d_in[0];
    float* out = (float*)d_out;

    dim3 grid(GX, BATCH);
    dh_fused_kernel<<<grid, 256>>>(x, out);
}

// round 3
// speedup vs baseline: 1.4048x; 1.2113x over previous
#include <cuda_runtime.h>
#include <cuda_bf16.h>

#define BATCH 4
#define HW    65536           // 256*256 pixels per (batch,channel)
#define NF2   (HW / 2)        // 32768 float2s per channel
#define KBINS 512             // 8^3 bins
#define GX    74              // blocks/batch -> 296 CTAs = exactly 2/SM
#define NTHR  512             // 32 warps/SM at 2 CTAs/SM (occ 50%)
// -1 / (49 * 2*sigma^2), sigma = 0.02
#define NEG_COEF (-25.510204081632653f)
// tail truncation: far-bin relative weight at f=0.30 is exp(-25.51*0.4)=3.7e-5
#define TLO 0.30f
#define THI 0.70f

// Scratch (no cudaMalloc). Zero at module load; last block per batch resets
// it each run, preserving the invariant across graph replays.
__device__ float        g_hist[BATCH * KBINS];
__device__ unsigned int g_count[BATCH];

__global__ __launch_bounds__(NTHR, 2)
void dh_fused_kernel(const float* __restrict__ x, float* __restrict__ out) {
    __shared__ float sh[KBINS];
    __shared__ float red[16];
    __shared__ int   s_last;

    const int b   = blockIdx.y;
    const int tid = threadIdx.x;

    sh[tid] = 0.0f;                 // 512 threads, 512 bins: one store each
    __syncthreads();

    // per-block contiguous float2 range: 442 or 443 per block (<= 512)
    const float* __restrict__ xb = x + (size_t)b * 3 * HW;
    const int start = (int)(((long long)blockIdx.x       * NF2) / GX);
    const int end   = (int)(((long long)(blockIdx.x + 1) * NF2) / GX);
    const int i2    = start + tid;

    if (i2 < end) {
        const float2 vx2 = __ldg((const float2*)(xb)          + i2);
        const float2 vy2 = __ldg((const float2*)(xb +     HW) + i2);
        const float2 vz2 = __ldg((const float2*)(xb + 2 * HW) + i2);
        const float* vxp = (const float*)&vx2;
        const float* vyp = (const float*)&vy2;
        const float* vzp = (const float*)&vz2;

        #pragma unroll
        for (int j = 0; j < 2; ++j) {
            const float tx = vxp[j] * 7.0f;
            const float ty = vyp[j] * 7.0f;
            const float tz = vzp[j] * 7.0f;
            const int ix = min((int)tx, 6);
            const int iy = min((int)ty, 6);
            const int iz = min((int)tz, 6);
            const float fx = tx - (float)ix;
            const float fy = ty - (float)iy;
            const float fz = tz - (float)iz;
            const float gx = 1.0f - fx, gy = 1.0f - fy, gz = 1.0f - fz;

            const float wx0 = __expf(NEG_COEF * fx * fx);
            const float wx1 = __expf(NEG_COEF * gx * gx);
            const float wy0 = __expf(NEG_COEF * fy * fy);
            const float wy1 = __expf(NEG_COEF * gy * gy);
            float       wz0 = __expf(NEG_COEF * fz * fz);
            float       wz1 = __expf(NEG_COEF * gz * gz);

            // exact per-pixel normalizer (all 6 weights; +1e-8 matters)
            const float S   = (wx0 + wx1) * (wy0 + wy1) * (wz0 + wz1);
            const float inv = __fdividef(1.0f, S + 1e-8f);
            wz0 *= inv;
            wz1 *= inv;

            const bool px0 = fx < THI, px1 = fx > TLO;
            const bool py0 = fy < THI, py1 = fy > TLO;
            const bool pz0 = fz < THI, pz1 = fz > TLO;

            const float wyz00 = wy0 * wz0, wyz01 = wy0 * wz1;
            const float wyz10 = wy1 * wz0, wyz11 = wy1 * wz1;
            const int base = ix * 64 + iy * 8 + iz;

            if (px0 && py0 && pz0) atomicAdd(&sh[base +  0], wx0 * wyz00);
            if (px0 && py0 && pz1) atomicAdd(&sh[base +  1], wx0 * wyz01);
            if (px0 && py1 && pz0) atomicAdd(&sh[base +  8], wx0 * wyz10);
            if (px0 && py1 && pz1) atomicAdd(&sh[base +  9], wx0 * wyz11);
            if (px1 && py0 && pz0) atomicAdd(&sh[base + 64], wx1 * wyz00);
            if (px1 && py0 && pz1) atomicAdd(&sh[base + 65], wx1 * wyz01);
            if (px1 && py1 && pz0) atomicAdd(&sh[base + 72], wx1 * wyz10);
            if (px1 && py1 && pz1) atomicAdd(&sh[base + 73], wx1 * wyz11);
        }
    }

    __syncthreads();

    // flush block-private histogram: one bin per thread
    {
        const float v = sh[tid];
        if (v != 0.0f) atomicAdd(&g_hist[b * KBINS + tid], v);
    }

    // last block per batch normalizes, writes out, resets scratch
    __threadfence();
    if (tid == 0) {
        const unsigned t = atomicAdd(&g_count[b], 1u);
        s_last = (t == gridDim.x - 1) ? 1 : 0;
    }
    __syncthreads();

    if (s_last) {
        __threadfence();
        const float v = __ldcg(&g_hist[b * KBINS + tid]);

        float s = v;
        #pragma unroll
        for (int o = 16; o > 0; o >>= 1) s += __shfl_xor_sync(0xffffffffu, s, o);
        if ((tid & 31) == 0) red[tid >> 5] = s;
        __syncthreads();

        float total = 0.0f;
        #pragma unroll
        for (int k = 0; k < 16; ++k) total += red[k];

        out[b * KBINS + tid] = v * __fdividef(1.0f, total + 1e-8f);

        // restore zero-invariant for the next graph replay
        g_hist[b * KBINS + tid] = 0.0f;
        if (tid == 0) g_count[b] = 0u;
    }
}

extern "C" void kernel_launch(void* const* d_in, const int* in_sizes, int n_in,
                              void* d_out, int out_size) {
    const float* x = (const float*)d_in[0];
    float* out = (float*)d_out;

    dim3 grid(GX, BATCH);
    dh_fused_kernel<<<grid, NTHR>>>(x, out);
}